// round 12
// baseline (speedup 1.0000x reference)
#include <cuda_runtime.h>
#include <cuda_bf16.h>
#include <cstdint>

// Problem constants
#define N_ROWS 8192
#define DIMK   1024
#define HALF_N 4096
#define INV_T  (1.0f / 0.07f)

#define TILE 128
#define KCH  64
#define KITERS 16
#define NBLK 64
#define NTRI 2080
#define NSPLIT 24                     // last tiles split into N-halves
#define NFULL (NTRI - NSPLIT)         // 2056
#define GRID (NFULL + 2 * NSPLIT)     // 2104

#define SMEM_DYN (3 * 2 * TILE * 128) // 96 KB (full-tile stages)

// Scratch (allocation-free rule: __device__ globals)
__device__ __nv_bfloat16 g_fb[N_ROWS * DIMK];
__device__ float         g_sumexp[N_ROWS];
__device__ float         g_pos[N_ROWS];
__device__ unsigned int  g_done;

// ---------------------------------------------------------------------------
__device__ __forceinline__ uint32_t smem_u32(const void* p) {
    uint32_t a;
    asm("{ .reg .u64 t; cvta.to.shared.u64 t, %1; cvt.u32.u64 %0, t; }" : "=r"(a) : "l"(p));
    return a;
}
#define CP16(dst, src) \
    asm volatile("cp.async.cg.shared.global [%0], [%1], 16;" :: "r"(dst), "l"(src) : "memory")
#define CP_COMMIT() asm volatile("cp.async.commit_group;" ::: "memory")
#define CP_WAIT(n)  asm volatile("cp.async.wait_group %0;" :: "n"(n) : "memory")

#define LDSM_X4(r0, r1, r2, r3, addr)                                        \
    asm volatile("ldmatrix.sync.aligned.m8n8.x4.shared.b16 {%0,%1,%2,%3}, [%4];" \
        : "=r"(r0), "=r"(r1), "=r"(r2), "=r"(r3) : "r"(addr))

#define MMA_BF16(d, a, b)                                                    \
    asm volatile("mma.sync.aligned.m16n8k16.row.col.f32.bf16.bf16.f32 "      \
        "{%0,%1,%2,%3}, {%4,%5,%6,%7}, {%8,%9}, {%0,%1,%2,%3};"              \
        : "+f"((d)[0]), "+f"((d)[1]), "+f"((d)[2]), "+f"((d)[3])             \
        : "r"((a)[0]), "r"((a)[1]), "r"((a)[2]), "r"((a)[3]),                \
          "r"((b)[0]), "r"((b)[1]))

__device__ __forceinline__ uint32_t sw_off(int row, int kc) {
    return (uint32_t)(row * 128 + ((kc ^ (row & 7)) << 4));
}

// ---------------------------------------------------------------------------
// Kernel A: normalize rows -> g_fb (bf16). One warp per row, shuffle-only.
// ---------------------------------------------------------------------------
__global__ void norm_kernel(const float* __restrict__ in, float* __restrict__ out) {
    const int warp = threadIdx.x >> 5;
    const int lane = threadIdx.x & 31;
    const int r = blockIdx.x * 16 + warp;

    const float4* src = reinterpret_cast<const float4*>(in + (size_t)r * DIMK);
    float4 v[8];
    float ss = 0.f;
    #pragma unroll
    for (int i = 0; i < 8; i++) {
        v[i] = src[lane + i * 32];
        ss += v[i].x * v[i].x + v[i].y * v[i].y + v[i].z * v[i].z + v[i].w * v[i].w;
    }
    #pragma unroll
    for (int m = 16; m; m >>= 1) ss += __shfl_xor_sync(0xffffffffu, ss, m);
    const float inv = rsqrtf(ss);

    uint2* dst = reinterpret_cast<uint2*>(g_fb + (size_t)r * DIMK);
    #pragma unroll
    for (int i = 0; i < 8; i++) {
        __nv_bfloat162 b0 = __floats2bfloat162_rn(v[i].x * inv, v[i].y * inv);
        __nv_bfloat162 b1 = __floats2bfloat162_rn(v[i].z * inv, v[i].w * inv);
        dst[lane + i * 32] = make_uint2(*reinterpret_cast<uint32_t*>(&b0),
                                        *reinterpret_cast<uint32_t*>(&b1));
    }
    if (lane == 0) g_sumexp[r] = 0.0f;
    if (r == 0 && lane == 0) { out[0] = 0.0f; g_done = 0u; }   // reset per call
}

// ---------------------------------------------------------------------------
// Tile worker, templated on NI (per-warp n-blocks of 8 cols).
// NI=8: 128x128 tile (warp tile 32x64). NI=4: 128x64 half (warp tile 32x32).
// 8 warps = 4(M) x 2(N). 3-stage cp.async pipeline, 1 barrier per K-iter.
// ---------------------------------------------------------------------------
template<int NI>
__device__ __forceinline__ void run_tile(
    uint32_t sbase, int rowBase, int colBase, bool diag, bool posTile, int tid)
{
    const int lane = tid & 31;
    const int wid = tid >> 5;
    const int warp_m = wid & 3;       // 0..3 (32 rows each)
    const int warp_n = wid >> 2;      // 0..1 (NI*8 cols each)
    const int BROWS = NI * 16;        // B rows: 128 or 64
    const int STAGE = TILE * 128 + BROWS * 128;

    uint32_t sAu[3], sBu[3];
    #pragma unroll
    for (int s = 0; s < 3; s++) {
        sAu[s] = sbase + s * STAGE;
        sBu[s] = sAu[s] + TILE * 128;
    }

    float acc[2][NI][4];
    #pragma unroll
    for (int mi = 0; mi < 2; mi++)
        #pragma unroll
        for (int ni = 0; ni < NI; ni++)
            #pragma unroll
            for (int k = 0; k < 4; k++) acc[mi][ni][k] = 0.f;

    auto load_tile = [&](int stage, int k0) {
        #pragma unroll
        for (int i = 0; i < 4; i++) {
            int c = tid + i * 256;
            int row = c >> 3, kc = c & 7;
            CP16(sAu[stage] + sw_off(row, kc),
                 g_fb + (size_t)(rowBase + row) * DIMK + k0 + kc * 8);
        }
        #pragma unroll
        for (int i = 0; i < BROWS / 32; i++) {
            int c = tid + i * 256;
            int row = c >> 3, kc = c & 7;
            CP16(sBu[stage] + sw_off(row, kc),
                 g_fb + (size_t)(colBase + row) * DIMK + k0 + kc * 8);
        }
        CP_COMMIT();
    };

    load_tile(0, 0);
    load_tile(1, KCH);

    #pragma unroll 1
    for (int it = 0; it < KITERS; it++) {
        CP_WAIT(1);
        __syncthreads();

        if (it + 2 < KITERS) load_tile((it + 2) % 3, (it + 2) * KCH);
        else CP_COMMIT();

        const uint32_t a_base = sAu[it % 3];
        const uint32_t b_base = sBu[it % 3];

        #pragma unroll
        for (int ks = 0; ks < 4; ks++) {
            uint32_t a[2][4];
            #pragma unroll
            for (int mi = 0; mi < 2; mi++) {
                int row = warp_m * 32 + mi * 16 + (lane & 15);
                int kc = ks * 2 + (lane >> 4);
                LDSM_X4(a[mi][0], a[mi][1], a[mi][2], a[mi][3],
                        a_base + sw_off(row, kc));
            }
            uint32_t b[NI][2];
            #pragma unroll
            for (int nq = 0; nq < NI / 2; nq++) {
                int nrow = warp_n * (NI * 8) + nq * 16 + (((lane >> 4) << 3) | (lane & 7));
                int kc = ks * 2 + ((lane >> 3) & 1);
                uint32_t t0, t1, t2, t3;
                LDSM_X4(t0, t1, t2, t3, b_base + sw_off(nrow, kc));
                b[nq * 2][0] = t0;     b[nq * 2][1] = t1;
                b[nq * 2 + 1][0] = t2; b[nq * 2 + 1][1] = t3;
            }
            #pragma unroll
            for (int mi = 0; mi < 2; mi++)
                #pragma unroll
                for (int ni = 0; ni < NI; ni++)
                    MMA_BF16(acc[mi][ni], a[mi], b[ni]);
        }
    }

    // ---- epilogue: direct global atomics (no smem, no extra barriers) ----
    const int g = lane >> 2;
    const int q4 = lane & 3;

    float csE[NI], csO[NI];
    #pragma unroll
    for (int ni = 0; ni < NI; ni++) { csE[ni] = 0.f; csO[ni] = 0.f; }

    #pragma unroll
    for (int mi = 0; mi < 2; mi++) {
        float rs0 = 0.f, rs1 = 0.f;
        const int ra = rowBase + warp_m * 32 + mi * 16 + g;
        const int rb = ra + 8;
        #pragma unroll
        for (int ni = 0; ni < NI; ni++) {
            const int cb = colBase + warp_n * (NI * 8) + ni * 8 + q4 * 2;
            const float v0 = acc[mi][ni][0], v1 = acc[mi][ni][1];
            const float v2 = acc[mi][ni][2], v3 = acc[mi][ni][3];

            if (posTile) {
                if (cb     == ra + HALF_N) { g_pos[ra] = v0; g_pos[cb]     = v0; }
                if (cb + 1 == ra + HALF_N) { g_pos[ra] = v1; g_pos[cb + 1] = v1; }
                if (cb     == rb + HALF_N) { g_pos[rb] = v2; g_pos[cb]     = v2; }
                if (cb + 1 == rb + HALF_N) { g_pos[rb] = v3; g_pos[cb + 1] = v3; }
            }

            float e0 = __expf(v0 * INV_T);
            float e1 = __expf(v1 * INV_T);
            float e2 = __expf(v2 * INV_T);
            float e3 = __expf(v3 * INV_T);
            if (ra == cb)     e0 = 0.f;
            if (ra == cb + 1) e1 = 0.f;
            if (rb == cb)     e2 = 0.f;
            if (rb == cb + 1) e3 = 0.f;
            rs0 += e0 + e1;
            rs1 += e2 + e3;
            csE[ni] += e0 + e2;
            csO[ni] += e1 + e3;
        }
        rs0 += __shfl_xor_sync(0xffffffffu, rs0, 1);
        rs0 += __shfl_xor_sync(0xffffffffu, rs0, 2);
        rs1 += __shfl_xor_sync(0xffffffffu, rs1, 1);
        rs1 += __shfl_xor_sync(0xffffffffu, rs1, 2);
        if (q4 == 0) {
            atomicAdd(&g_sumexp[ra], rs0);
            atomicAdd(&g_sumexp[rb], rs1);
        }
    }

    #pragma unroll
    for (int ni = 0; ni < NI; ni++) {
        float vE = csE[ni], vO = csO[ni];
        #pragma unroll
        for (int m = 4; m <= 16; m <<= 1) {
            vE += __shfl_xor_sync(0xffffffffu, vE, m);
            vO += __shfl_xor_sync(0xffffffffu, vO, m);
        }
        if (lane < 4 && !diag) {
            const int c = colBase + warp_n * (NI * 8) + ni * 8 + q4 * 2;
            atomicAdd(&g_sumexp[c], vE);
            atomicAdd(&g_sumexp[c + 1], vO);
        }
    }
}

// ---------------------------------------------------------------------------
// Kernel B dispatcher: map blockIdx -> (tile, half), run, and have the LAST
// CTA fold the final loss reduction (threadFenceReduction pattern).
// ---------------------------------------------------------------------------
__global__ __launch_bounds__(256, 2) void simexp_kernel(float* __restrict__ out) {
    extern __shared__ __align__(16) char dsmem[];
    const int tid = threadIdx.x;

    int t, colOff = 0;
    bool half = false;
    if (blockIdx.x < NFULL) {
        t = blockIdx.x;
    } else {
        int e = blockIdx.x - NFULL;
        t = NFULL + (e >> 1);
        colOff = (e & 1) * 64;
        half = true;
    }

    // linear tile id -> (bi, bj), bi <= bj
    int bi = (int)(64.5f - sqrtf(64.5f * 64.5f - 2.0f * (float)t));
    if (bi < 0) bi = 0;
    if (bi >= NBLK) bi = NBLK - 1;
    #pragma unroll 1
    while (bi + 1 <= NBLK - 1 && (bi + 1) * NBLK - ((bi + 1) * bi) / 2 <= t) bi++;
    #pragma unroll 1
    while (bi > 0 && bi * NBLK - (bi * (bi - 1)) / 2 > t) bi--;
    const int bj = bi + (t - (bi * NBLK - (bi * (bi - 1)) / 2));

    const int rowBase = bi * TILE;
    const int colBase = bj * TILE + colOff;
    const bool diag = (bi == bj);
    const bool posTile = (bj - bi == 32);

    const uint32_t sbase = smem_u32(dsmem);
    if (half)
        run_tile<4>(sbase, rowBase, colBase, diag, posTile, tid);
    else
        run_tile<8>(sbase, rowBase, colBase, diag, posTile, tid);

    // ---- last-CTA fused finalize ----
    __shared__ unsigned int s_last;
    __threadfence();                 // all this thread's writes visible (release)
    __syncthreads();                 // whole CTA's writes fenced
    if (tid == 0)
        s_last = (atomicAdd(&g_done, 1u) == (unsigned)(GRID - 1)) ? 1u : 0u;
    __syncthreads();

    if (s_last) {
        __threadfence();             // acquire side
        float s = 0.f;
        #pragma unroll 1
        for (int i = tid; i < N_ROWS; i += 256)
            s += logf(__ldcg(&g_sumexp[i])) - __ldcg(&g_pos[i]) * INV_T;
        #pragma unroll
        for (int m = 16; m; m >>= 1) s += __shfl_xor_sync(0xffffffffu, s, m);
        __shared__ float ws[8];
        if ((tid & 31) == 0) ws[tid >> 5] = s;
        __syncthreads();
        if (tid == 0) {
            float tot = 0.f;
            #pragma unroll
            for (int k = 0; k < 8; k++) tot += ws[k];
            out[0] = tot * (1.0f / N_ROWS);
        }
    }
}

// ---------------------------------------------------------------------------
extern "C" void kernel_launch(void* const* d_in, const int* in_sizes, int n_in,
                              void* d_out, int out_size) {
    const float* features = (const float*)d_in[0];
    float* out = (float*)d_out;

    static bool configured = false;
    if (!configured) {
        cudaFuncSetAttribute(simexp_kernel,
                             cudaFuncAttributeMaxDynamicSharedMemorySize, SMEM_DYN);
        configured = true;
    }

    norm_kernel<<<N_ROWS / 16, 512>>>(features, out);
    simexp_kernel<<<GRID, 256, SMEM_DYN>>>(out);
}

// round 13
// speedup vs baseline: 1.4609x; 1.4609x over previous
#include <cuda_runtime.h>
#include <cuda_bf16.h>
#include <cstdint>

// Problem constants
#define N_ROWS 8192
#define DIMK   1024
#define HALF_N 4096
#define INV_T  (1.0f / 0.07f)
#define EXP2_SCALE (1.4426950408889634f / 0.07f)   // log2(e)/T, folded

#define TILE 128
#define KCH  64
#define KITERS 16
#define NBLK 64
#define NTRI 2080
#define NSPLIT 24                     // last tiles split into N-halves
#define NFULL (NTRI - NSPLIT)         // 2056
#define GRID (NFULL + 2 * NSPLIT)     // 2104

#define SMEM_DYN (3 * 2 * TILE * 128) // 96 KB (full-tile stages)

// Scratch (allocation-free rule: __device__ globals)
__device__ __nv_bfloat16 g_fb[N_ROWS * DIMK];
__device__ float         g_sumexp[N_ROWS];
__device__ float         g_pos[N_ROWS];

// ---------------------------------------------------------------------------
__device__ __forceinline__ uint32_t smem_u32(const void* p) {
    uint32_t a;
    asm("{ .reg .u64 t; cvta.to.shared.u64 t, %1; cvt.u32.u64 %0, t; }" : "=r"(a) : "l"(p));
    return a;
}
#define CP16(dst, src) \
    asm volatile("cp.async.cg.shared.global [%0], [%1], 16;" :: "r"(dst), "l"(src) : "memory")
#define CP_COMMIT() asm volatile("cp.async.commit_group;" ::: "memory")
#define CP_WAIT(n)  asm volatile("cp.async.wait_group %0;" :: "n"(n) : "memory")

#define LDSM_X4(r0, r1, r2, r3, addr)                                        \
    asm volatile("ldmatrix.sync.aligned.m8n8.x4.shared.b16 {%0,%1,%2,%3}, [%4];" \
        : "=r"(r0), "=r"(r1), "=r"(r2), "=r"(r3) : "r"(addr))

#define MMA_BF16(d, a, b)                                                    \
    asm volatile("mma.sync.aligned.m16n8k16.row.col.f32.bf16.bf16.f32 "      \
        "{%0,%1,%2,%3}, {%4,%5,%6,%7}, {%8,%9}, {%0,%1,%2,%3};"              \
        : "+f"((d)[0]), "+f"((d)[1]), "+f"((d)[2]), "+f"((d)[3])             \
        : "r"((a)[0]), "r"((a)[1]), "r"((a)[2]), "r"((a)[3]),                \
          "r"((b)[0]), "r"((b)[1]))

__device__ __forceinline__ uint32_t sw_off(int row, int kc) {
    return (uint32_t)(row * 128 + ((kc ^ (row & 7)) << 4));
}

// ---------------------------------------------------------------------------
// Kernel A: normalize rows -> g_fb (bf16). One warp per row, shuffle-only.
// ---------------------------------------------------------------------------
__global__ void norm_kernel(const float* __restrict__ in, float* __restrict__ out) {
    const int warp = threadIdx.x >> 5;
    const int lane = threadIdx.x & 31;
    const int r = blockIdx.x * 16 + warp;

    const float4* src = reinterpret_cast<const float4*>(in + (size_t)r * DIMK);
    float4 v[8];
    float ss = 0.f;
    #pragma unroll
    for (int i = 0; i < 8; i++) {
        v[i] = src[lane + i * 32];
        ss += v[i].x * v[i].x + v[i].y * v[i].y + v[i].z * v[i].z + v[i].w * v[i].w;
    }
    #pragma unroll
    for (int m = 16; m; m >>= 1) ss += __shfl_xor_sync(0xffffffffu, ss, m);
    const float inv = rsqrtf(ss);

    uint2* dst = reinterpret_cast<uint2*>(g_fb + (size_t)r * DIMK);
    #pragma unroll
    for (int i = 0; i < 8; i++) {
        __nv_bfloat162 b0 = __floats2bfloat162_rn(v[i].x * inv, v[i].y * inv);
        __nv_bfloat162 b1 = __floats2bfloat162_rn(v[i].z * inv, v[i].w * inv);
        dst[lane + i * 32] = make_uint2(*reinterpret_cast<uint32_t*>(&b0),
                                        *reinterpret_cast<uint32_t*>(&b1));
    }
    if (lane == 0) g_sumexp[r] = 0.0f;
    if (r == 0 && lane == 0) out[0] = 0.0f;   // d_out poisoned
}

// ---------------------------------------------------------------------------
// Tile worker, templated on NI (per-warp n-blocks of 8 cols).
// NI=8: 128x128 tile (warp tile 32x64). NI=4: 128x64 half (warp tile 32x32).
// 8 warps = 4(M) x 2(N). 3-stage cp.async pipeline, 1 barrier per K-iter.
// ---------------------------------------------------------------------------
template<int NI>
__device__ __forceinline__ void run_tile(
    uint32_t sbase, int rowBase, int colBase, bool diag, bool posTile, int tid)
{
    const int lane = tid & 31;
    const int wid = tid >> 5;
    const int warp_m = wid & 3;       // 0..3 (32 rows each)
    const int warp_n = wid >> 2;      // 0..1 (NI*8 cols each)
    const int BROWS = NI * 16;        // B rows: 128 or 64
    const int STAGE = TILE * 128 + BROWS * 128;

    uint32_t sAu[3], sBu[3];
    #pragma unroll
    for (int s = 0; s < 3; s++) {
        sAu[s] = sbase + s * STAGE;
        sBu[s] = sAu[s] + TILE * 128;
    }

    float acc[2][NI][4];
    #pragma unroll
    for (int mi = 0; mi < 2; mi++)
        #pragma unroll
        for (int ni = 0; ni < NI; ni++)
            #pragma unroll
            for (int k = 0; k < 4; k++) acc[mi][ni][k] = 0.f;

    auto load_tile = [&](int stage, int k0) {
        #pragma unroll
        for (int i = 0; i < 4; i++) {
            int c = tid + i * 256;
            int row = c >> 3, kc = c & 7;
            CP16(sAu[stage] + sw_off(row, kc),
                 g_fb + (size_t)(rowBase + row) * DIMK + k0 + kc * 8);
        }
        #pragma unroll
        for (int i = 0; i < BROWS / 32; i++) {
            int c = tid + i * 256;
            int row = c >> 3, kc = c & 7;
            CP16(sBu[stage] + sw_off(row, kc),
                 g_fb + (size_t)(colBase + row) * DIMK + k0 + kc * 8);
        }
        CP_COMMIT();
    };

    load_tile(0, 0);
    load_tile(1, KCH);

    #pragma unroll 1
    for (int it = 0; it < KITERS; it++) {
        CP_WAIT(1);
        __syncthreads();

        if (it + 2 < KITERS) load_tile((it + 2) % 3, (it + 2) * KCH);
        else CP_COMMIT();

        const uint32_t a_base = sAu[it % 3];
        const uint32_t b_base = sBu[it % 3];

        #pragma unroll
        for (int ks = 0; ks < 4; ks++) {
            uint32_t a[2][4];
            #pragma unroll
            for (int mi = 0; mi < 2; mi++) {
                int row = warp_m * 32 + mi * 16 + (lane & 15);
                int kc = ks * 2 + (lane >> 4);
                LDSM_X4(a[mi][0], a[mi][1], a[mi][2], a[mi][3],
                        a_base + sw_off(row, kc));
            }
            uint32_t b[NI][2];
            #pragma unroll
            for (int nq = 0; nq < NI / 2; nq++) {
                int nrow = warp_n * (NI * 8) + nq * 16 + (((lane >> 4) << 3) | (lane & 7));
                int kc = ks * 2 + ((lane >> 3) & 1);
                uint32_t t0, t1, t2, t3;
                LDSM_X4(t0, t1, t2, t3, b_base + sw_off(nrow, kc));
                b[nq * 2][0] = t0;     b[nq * 2][1] = t1;
                b[nq * 2 + 1][0] = t2; b[nq * 2 + 1][1] = t3;
            }
            #pragma unroll
            for (int mi = 0; mi < 2; mi++)
                #pragma unroll
                for (int ni = 0; ni < NI; ni++)
                    MMA_BF16(acc[mi][ni], a[mi], b[ni]);
        }
    }

    // ---- epilogue: direct global atomics (no smem, no extra barriers) ----
    const int g = lane >> 2;
    const int q4 = lane & 3;

    float csE[NI], csO[NI];
    #pragma unroll
    for (int ni = 0; ni < NI; ni++) { csE[ni] = 0.f; csO[ni] = 0.f; }

    #pragma unroll
    for (int mi = 0; mi < 2; mi++) {
        float rs0 = 0.f, rs1 = 0.f;
        const int ra = rowBase + warp_m * 32 + mi * 16 + g;
        const int rb = ra + 8;
        #pragma unroll
        for (int ni = 0; ni < NI; ni++) {
            const int cb = colBase + warp_n * (NI * 8) + ni * 8 + q4 * 2;
            const float v0 = acc[mi][ni][0], v1 = acc[mi][ni][1];
            const float v2 = acc[mi][ni][2], v3 = acc[mi][ni][3];

            if (posTile) {
                if (cb     == ra + HALF_N) { g_pos[ra] = v0; g_pos[cb]     = v0; }
                if (cb + 1 == ra + HALF_N) { g_pos[ra] = v1; g_pos[cb + 1] = v1; }
                if (cb     == rb + HALF_N) { g_pos[rb] = v2; g_pos[cb]     = v2; }
                if (cb + 1 == rb + HALF_N) { g_pos[rb] = v3; g_pos[cb + 1] = v3; }
            }

            float e0 = exp2f(v0 * EXP2_SCALE);
            float e1 = exp2f(v1 * EXP2_SCALE);
            float e2 = exp2f(v2 * EXP2_SCALE);
            float e3 = exp2f(v3 * EXP2_SCALE);
            if (ra == cb)     e0 = 0.f;
            if (ra == cb + 1) e1 = 0.f;
            if (rb == cb)     e2 = 0.f;
            if (rb == cb + 1) e3 = 0.f;
            rs0 += e0 + e1;
            rs1 += e2 + e3;
            csE[ni] += e0 + e2;
            csO[ni] += e1 + e3;
        }
        rs0 += __shfl_xor_sync(0xffffffffu, rs0, 1);
        rs0 += __shfl_xor_sync(0xffffffffu, rs0, 2);
        rs1 += __shfl_xor_sync(0xffffffffu, rs1, 1);
        rs1 += __shfl_xor_sync(0xffffffffu, rs1, 2);
        if (q4 == 0) {
            atomicAdd(&g_sumexp[ra], rs0);
            atomicAdd(&g_sumexp[rb], rs1);
        }
    }

    #pragma unroll
    for (int ni = 0; ni < NI; ni++) {
        float vE = csE[ni], vO = csO[ni];
        #pragma unroll
        for (int m = 4; m <= 16; m <<= 1) {
            vE += __shfl_xor_sync(0xffffffffu, vE, m);
            vO += __shfl_xor_sync(0xffffffffu, vO, m);
        }
        if (lane < 4 && !diag) {
            const int c = colBase + warp_n * (NI * 8) + ni * 8 + q4 * 2;
            atomicAdd(&g_sumexp[c], vE);
            atomicAdd(&g_sumexp[c + 1], vO);
        }
    }
}

// ---------------------------------------------------------------------------
// Kernel B dispatcher: map blockIdx -> (tile, half) and run.
// ---------------------------------------------------------------------------
__global__ __launch_bounds__(256, 2) void simexp_kernel() {
    extern __shared__ __align__(16) char dsmem[];
    const int tid = threadIdx.x;

    int t, colOff = 0;
    bool half = false;
    if (blockIdx.x < NFULL) {
        t = blockIdx.x;
    } else {
        int e = blockIdx.x - NFULL;
        t = NFULL + (e >> 1);
        colOff = (e & 1) * 64;
        half = true;
    }

    // linear tile id -> (bi, bj), bi <= bj
    int bi = (int)(64.5f - sqrtf(64.5f * 64.5f - 2.0f * (float)t));
    if (bi < 0) bi = 0;
    if (bi >= NBLK) bi = NBLK - 1;
    #pragma unroll 1
    while (bi + 1 <= NBLK - 1 && (bi + 1) * NBLK - ((bi + 1) * bi) / 2 <= t) bi++;
    #pragma unroll 1
    while (bi > 0 && bi * NBLK - (bi * (bi - 1)) / 2 > t) bi--;
    const int bj = bi + (t - (bi * NBLK - (bi * (bi - 1)) / 2));

    const int rowBase = bi * TILE;
    const int colBase = bj * TILE + colOff;
    const bool diag = (bi == bj);
    const bool posTile = (bj - bi == 32);

    const uint32_t sbase = smem_u32(dsmem);
    if (half)
        run_tile<4>(sbase, rowBase, colBase, diag, posTile, tid);
    else
        run_tile<8>(sbase, rowBase, colBase, diag, posTile, tid);
}

// ---------------------------------------------------------------------------
// Kernel C: finalize. loss_i = log(sumexp_i) - pos_i / T ; mean via atomics.
// ---------------------------------------------------------------------------
__global__ void finalize_kernel(float* __restrict__ out) {
    int i = blockIdx.x * 256 + threadIdx.x;
    float loss = logf(g_sumexp[i]) - g_pos[i] * INV_T;

    #pragma unroll
    for (int m = 16; m; m >>= 1) loss += __shfl_xor_sync(0xffffffffu, loss, m);
    __shared__ float ws[8];
    if ((threadIdx.x & 31) == 0) ws[threadIdx.x >> 5] = loss;
    __syncthreads();
    if (threadIdx.x == 0) {
        float s = 0.f;
        #pragma unroll
        for (int k = 0; k < 8; k++) s += ws[k];
        atomicAdd(out, s * (1.0f / N_ROWS));
    }
}

// ---------------------------------------------------------------------------
extern "C" void kernel_launch(void* const* d_in, const int* in_sizes, int n_in,
                              void* d_out, int out_size) {
    const float* features = (const float*)d_in[0];
    float* out = (float*)d_out;

    static bool configured = false;
    if (!configured) {
        cudaFuncSetAttribute(simexp_kernel,
                             cudaFuncAttributeMaxDynamicSharedMemorySize, SMEM_DYN);
        configured = true;
    }

    norm_kernel<<<N_ROWS / 16, 512>>>(features, out);
    simexp_kernel<<<GRID, 256, SMEM_DYN>>>();
    finalize_kernel<<<N_ROWS / 256, 256>>>(out);
}

// round 15
// speedup vs baseline: 1.4999x; 1.0267x over previous
#include <cuda_runtime.h>
#include <cuda_fp16.h>
#include <cstdint>

// Problem constants
#define N_ROWS 8192
#define DIMK   1024
#define HALF_N 4096
#define INV_T  (1.0f / 0.07f)
#define EXP2_SCALE (1.4426950408889634f / 0.07f)   // log2(e)/T, folded

#define TILE 128
#define KCH  64
#define KITERS 16
#define NBLK 64
#define NTRI 2080
#define NSPLIT 24                     // last tiles split into N-halves
#define NFULL (NTRI - NSPLIT)         // 2056
#define GRID (NFULL + 2 * NSPLIT)     // 2104

#define SMEM_DYN (2 * 2 * TILE * 128) // 64 KB (2-stage full-tile)

// Scratch (allocation-free rule: __device__ globals)
__device__ __half g_fb[N_ROWS * DIMK];   // normalized fp16
__device__ float  g_sumexp[N_ROWS];
__device__ float  g_pos[N_ROWS];

// ---------------------------------------------------------------------------
__device__ __forceinline__ uint32_t smem_u32(const void* p) {
    uint32_t a;
    asm("{ .reg .u64 t; cvta.to.shared.u64 t, %1; cvt.u32.u64 %0, t; }" : "=r"(a) : "l"(p));
    return a;
}
#define CP16(dst, src) \
    asm volatile("cp.async.cg.shared.global [%0], [%1], 16;" :: "r"(dst), "l"(src) : "memory")
#define CP_COMMIT() asm volatile("cp.async.commit_group;" ::: "memory")
#define CP_WAIT(n)  asm volatile("cp.async.wait_group %0;" :: "n"(n) : "memory")

#define LDSM_X4(r0, r1, r2, r3, addr)                                        \
    asm volatile("ldmatrix.sync.aligned.m8n8.x4.shared.b16 {%0,%1,%2,%3}, [%4];" \
        : "=r"(r0), "=r"(r1), "=r"(r2), "=r"(r3) : "r"(addr))

// fp16 in, fp16 accumulate. D = 2 packed regs = 4 halves, positionally
// matching the f32 variant: reg0 = (row g, col c|c+1), reg1 = (row g+8, ...).
#define MMA_F16(d, a, b)                                                     \
    asm volatile("mma.sync.aligned.m16n8k16.row.col.f16.f16.f16.f16 "        \
        "{%0,%1}, {%2,%3,%4,%5}, {%6,%7}, {%0,%1};"                          \
        : "+r"((d)[0]), "+r"((d)[1])                                         \
        : "r"((a)[0]), "r"((a)[1]), "r"((a)[2]), "r"((a)[3]),                \
          "r"((b)[0]), "r"((b)[1]))

__device__ __forceinline__ uint32_t sw_off(int row, int kc) {
    return (uint32_t)(row * 128 + ((kc ^ (row & 7)) << 4));
}

// ---------------------------------------------------------------------------
// Kernel A: normalize rows -> g_fb (fp16). One warp per row, shuffle-only.
// ---------------------------------------------------------------------------
__global__ void norm_kernel(const float* __restrict__ in, float* __restrict__ out) {
    const int warp = threadIdx.x >> 5;
    const int lane = threadIdx.x & 31;
    const int r = blockIdx.x * 16 + warp;

    const float4* src = reinterpret_cast<const float4*>(in + (size_t)r * DIMK);
    float4 v[8];
    float ss = 0.f;
    #pragma unroll
    for (int i = 0; i < 8; i++) {
        v[i] = src[lane + i * 32];
        ss += v[i].x * v[i].x + v[i].y * v[i].y + v[i].z * v[i].z + v[i].w * v[i].w;
    }
    #pragma unroll
    for (int m = 16; m; m >>= 1) ss += __shfl_xor_sync(0xffffffffu, ss, m);
    const float inv = rsqrtf(ss);

    uint2* dst = reinterpret_cast<uint2*>(g_fb + (size_t)r * DIMK);
    #pragma unroll
    for (int i = 0; i < 8; i++) {
        __half2 h0 = __floats2half2_rn(v[i].x * inv, v[i].y * inv);
        __half2 h1 = __floats2half2_rn(v[i].z * inv, v[i].w * inv);
        dst[lane + i * 32] = make_uint2(*reinterpret_cast<uint32_t*>(&h0),
                                        *reinterpret_cast<uint32_t*>(&h1));
    }
    if (lane == 0) g_sumexp[r] = 0.0f;
    if (r == 0 && lane == 0) out[0] = 0.0f;   // d_out poisoned
}

// ---------------------------------------------------------------------------
// Tile worker, templated on NI (per-warp n-blocks of 8 cols).
// NI=8: 128x128 tile (warp tile 32x64). NI=4: 128x64 half (warp tile 32x32).
// 8 warps = 4(M) x 2(N). 2-stage cp.async pipeline:
//   CP_WAIT(0) -> __syncthreads -> issue load(it+1) -> compute(it)
// (wait BEFORE barrier so all threads' copies are published — the R14 fix).
// ---------------------------------------------------------------------------
template<int NI>
__device__ __forceinline__ void run_tile(
    uint32_t sbase, int rowBase, int colBase, bool diag, bool posTile, int tid)
{
    const int lane = tid & 31;
    const int wid = tid >> 5;
    const int warp_m = wid & 3;       // 0..3 (32 rows each)
    const int warp_n = wid >> 2;      // 0..1 (NI*8 cols each)
    const int BROWS = NI * 16;        // B rows: 128 or 64
    const int STAGE = TILE * 128 + BROWS * 128;

    uint32_t sAu[2], sBu[2];
    #pragma unroll
    for (int s = 0; s < 2; s++) {
        sAu[s] = sbase + s * STAGE;
        sBu[s] = sAu[s] + TILE * 128;
    }

    uint32_t acc[2][NI][2];
    #pragma unroll
    for (int mi = 0; mi < 2; mi++)
        #pragma unroll
        for (int ni = 0; ni < NI; ni++) { acc[mi][ni][0] = 0u; acc[mi][ni][1] = 0u; }

    auto load_tile = [&](int stage, int k0) {
        #pragma unroll
        for (int i = 0; i < 4; i++) {
            int c = tid + i * 256;
            int row = c >> 3, kc = c & 7;
            CP16(sAu[stage] + sw_off(row, kc),
                 g_fb + (size_t)(rowBase + row) * DIMK + k0 + kc * 8);
        }
        #pragma unroll
        for (int i = 0; i < BROWS / 32; i++) {
            int c = tid + i * 256;
            int row = c >> 3, kc = c & 7;
            CP16(sBu[stage] + sw_off(row, kc),
                 g_fb + (size_t)(colBase + row) * DIMK + k0 + kc * 8);
        }
        CP_COMMIT();
    };

    load_tile(0, 0);

    #pragma unroll 1
    for (int it = 0; it < KITERS; it++) {
        CP_WAIT(0);                      // own copies of tile `it` complete
        __syncthreads();                 // publish all threads' copies;
                                         // compute(it-1) also done by all

        if (it + 1 < KITERS)             // overlaps with compute(it) below
            load_tile((it + 1) & 1, (it + 1) * KCH);

        const uint32_t a_base = sAu[it & 1];
        const uint32_t b_base = sBu[it & 1];

        #pragma unroll
        for (int ks = 0; ks < 4; ks++) {
            uint32_t a[2][4];
            #pragma unroll
            for (int mi = 0; mi < 2; mi++) {
                int row = warp_m * 32 + mi * 16 + (lane & 15);
                int kc = ks * 2 + (lane >> 4);
                LDSM_X4(a[mi][0], a[mi][1], a[mi][2], a[mi][3],
                        a_base + sw_off(row, kc));
            }
            uint32_t b[NI][2];
            #pragma unroll
            for (int nq = 0; nq < NI / 2; nq++) {
                int nrow = warp_n * (NI * 8) + nq * 16 + (((lane >> 4) << 3) | (lane & 7));
                int kc = ks * 2 + ((lane >> 3) & 1);
                uint32_t t0, t1, t2, t3;
                LDSM_X4(t0, t1, t2, t3, b_base + sw_off(nrow, kc));
                b[nq * 2][0] = t0;     b[nq * 2][1] = t1;
                b[nq * 2 + 1][0] = t2; b[nq * 2 + 1][1] = t3;
            }
            #pragma unroll
            for (int mi = 0; mi < 2; mi++)
                #pragma unroll
                for (int ni = 0; ni < NI; ni++)
                    MMA_F16(acc[mi][ni], a[mi], b[ni]);
        }
    }

    // ---- epilogue: unpack fp16 acc, exp2, diag mask, row/col sums ----
    const int g = lane >> 2;
    const int q4 = lane & 3;

    float csE[NI], csO[NI];
    #pragma unroll
    for (int ni = 0; ni < NI; ni++) { csE[ni] = 0.f; csO[ni] = 0.f; }

    #pragma unroll
    for (int mi = 0; mi < 2; mi++) {
        float rs0 = 0.f, rs1 = 0.f;
        const int ra = rowBase + warp_m * 32 + mi * 16 + g;
        const int rb = ra + 8;
        #pragma unroll
        for (int ni = 0; ni < NI; ni++) {
            const int cb = colBase + warp_n * (NI * 8) + ni * 8 + q4 * 2;
            const __half2 h0 = *reinterpret_cast<const __half2*>(&acc[mi][ni][0]);
            const __half2 h1 = *reinterpret_cast<const __half2*>(&acc[mi][ni][1]);
            const float v0 = __low2float(h0), v1 = __high2float(h0);
            const float v2 = __low2float(h1), v3 = __high2float(h1);

            if (posTile) {
                if (cb     == ra + HALF_N) { g_pos[ra] = v0; g_pos[cb]     = v0; }
                if (cb + 1 == ra + HALF_N) { g_pos[ra] = v1; g_pos[cb + 1] = v1; }
                if (cb     == rb + HALF_N) { g_pos[rb] = v2; g_pos[cb]     = v2; }
                if (cb + 1 == rb + HALF_N) { g_pos[rb] = v3; g_pos[cb + 1] = v3; }
            }

            float e0 = exp2f(v0 * EXP2_SCALE);
            float e1 = exp2f(v1 * EXP2_SCALE);
            float e2 = exp2f(v2 * EXP2_SCALE);
            float e3 = exp2f(v3 * EXP2_SCALE);
            if (ra == cb)     e0 = 0.f;
            if (ra == cb + 1) e1 = 0.f;
            if (rb == cb)     e2 = 0.f;
            if (rb == cb + 1) e3 = 0.f;
            rs0 += e0 + e1;
            rs1 += e2 + e3;
            csE[ni] += e0 + e2;
            csO[ni] += e1 + e3;
        }
        rs0 += __shfl_xor_sync(0xffffffffu, rs0, 1);
        rs0 += __shfl_xor_sync(0xffffffffu, rs0, 2);
        rs1 += __shfl_xor_sync(0xffffffffu, rs1, 1);
        rs1 += __shfl_xor_sync(0xffffffffu, rs1, 2);
        if (q4 == 0) {
            atomicAdd(&g_sumexp[ra], rs0);
            atomicAdd(&g_sumexp[rb], rs1);
        }
    }

    #pragma unroll
    for (int ni = 0; ni < NI; ni++) {
        float vE = csE[ni], vO = csO[ni];
        #pragma unroll
        for (int m = 4; m <= 16; m <<= 1) {
            vE += __shfl_xor_sync(0xffffffffu, vE, m);
            vO += __shfl_xor_sync(0xffffffffu, vO, m);
        }
        if (lane < 4 && !diag) {
            const int c = colBase + warp_n * (NI * 8) + ni * 8 + q4 * 2;
            atomicAdd(&g_sumexp[c], vE);
            atomicAdd(&g_sumexp[c + 1], vO);
        }
    }
}

// ---------------------------------------------------------------------------
// Kernel B dispatcher: map blockIdx -> (tile, half) and run.
// ---------------------------------------------------------------------------
__global__ __launch_bounds__(256, 3) void simexp_kernel() {
    extern __shared__ __align__(16) char dsmem[];
    const int tid = threadIdx.x;

    int t, colOff = 0;
    bool half = false;
    if (blockIdx.x < NFULL) {
        t = blockIdx.x;
    } else {
        int e = blockIdx.x - NFULL;
        t = NFULL + (e >> 1);
        colOff = (e & 1) * 64;
        half = true;
    }

    // linear tile id -> (bi, bj), bi <= bj
    int bi = (int)(64.5f - sqrtf(64.5f * 64.5f - 2.0f * (float)t));
    if (bi < 0) bi = 0;
    if (bi >= NBLK) bi = NBLK - 1;
    #pragma unroll 1
    while (bi + 1 <= NBLK - 1 && (bi + 1) * NBLK - ((bi + 1) * bi) / 2 <= t) bi++;
    #pragma unroll 1
    while (bi > 0 && bi * NBLK - (bi * (bi - 1)) / 2 > t) bi--;
    const int bj = bi + (t - (bi * NBLK - (bi * (bi - 1)) / 2));

    const int rowBase = bi * TILE;
    const int colBase = bj * TILE + colOff;
    const bool diag = (bi == bj);
    const bool posTile = (bj - bi == 32);

    const uint32_t sbase = smem_u32(dsmem);
    if (half)
        run_tile<4>(sbase, rowBase, colBase, diag, posTile, tid);
    else
        run_tile<8>(sbase, rowBase, colBase, diag, posTile, tid);
}

// ---------------------------------------------------------------------------
// Kernel C: finalize. loss_i = log(sumexp_i) - pos_i / T ; mean via atomics.
// ---------------------------------------------------------------------------
__global__ void finalize_kernel(float* __restrict__ out) {
    int i = blockIdx.x * 256 + threadIdx.x;
    float loss = logf(g_sumexp[i]) - g_pos[i] * INV_T;

    #pragma unroll
    for (int m = 16; m; m >>= 1) loss += __shfl_xor_sync(0xffffffffu, loss, m);
    __shared__ float ws[8];
    if ((threadIdx.x & 31) == 0) ws[threadIdx.x >> 5] = loss;
    __syncthreads();
    if (threadIdx.x == 0) {
        float s = 0.f;
        #pragma unroll
        for (int k = 0; k < 8; k++) s += ws[k];
        atomicAdd(out, s * (1.0f / N_ROWS));
    }
}

// ---------------------------------------------------------------------------
extern "C" void kernel_launch(void* const* d_in, const int* in_sizes, int n_in,
                              void* d_out, int out_size) {
    const float* features = (const float*)d_in[0];
    float* out = (float*)d_out;

    static bool configured = false;
    if (!configured) {
        cudaFuncSetAttribute(simexp_kernel,
                             cudaFuncAttributeMaxDynamicSharedMemorySize, SMEM_DYN);
        configured = true;
    }

    norm_kernel<<<N_ROWS / 16, 512>>>(features, out);
    simexp_kernel<<<GRID, 256, SMEM_DYN>>>();
    finalize_kernel<<<N_ROWS / 256, 256>>>(out);
}